// round 14
// baseline (speedup 1.0000x reference)
#include <cuda_runtime.h>
#include <cuda_fp16.h>
#include <cstdint>

#define NB 8192
#define ND 256
#define NK 8
#define NT 64
#define NTILE 2080        // 64*65/2 upper-triangular tiles
#define LOG2E_F 1.4426950408889634f
#define LN2_F   0.6931471805599453f
#define CH 32             // K elements per pipeline stage
#define SROW 40           // padded fp16 row (80B): conflict-free ldmatrix
#define BUFM (128 * SROW * 2)    // 10240 B per matrix per stage

// dynamic smem layout (bytes): 2 stages -> 4 CTAs/SM
#define OFF_SB   (2 * BUFM)
#define OFF_ROWA (4 * BUFM)
#define OFF_ROWB (OFF_ROWA + 1024)
#define OFF_COLA (OFF_ROWB + 1024)
#define OFF_COLB (OFF_COLA + 2048)
#define OFF_MIN  (OFF_COLB + 2048)
#define OFF_MAX  (OFF_MIN + 32)
#define SMEM_TOTAL (OFF_MAX + 32)       // 47168 B -> 4 CTAs/SM (188.7KB)

// ---------------- device scratch ----------------
__device__ __align__(16) __half g_z[NB * ND];
__device__ float g_Apart[NT * NB];               // [slot*NB + row]
__device__ float g_Bpart[NT * NB];
__device__ __align__(16) float g_uPos[NB * NK];
__device__ float g_uDiag[NB];
__device__ float g_red[512];
__device__ unsigned g_negMinK, g_negMaxK, g_pvMinK, g_pvMaxK;
__device__ unsigned g_cnt;
__device__ float g_C1;

// ---------------- helpers ----------------
__device__ __forceinline__ unsigned enc(float f) {
    unsigned b = __float_as_uint(f);
    return (b & 0x80000000u) ? ~b : (b | 0x80000000u);
}
__device__ __forceinline__ float dec(unsigned k) {
    unsigned b = (k & 0x80000000u) ? (k ^ 0x80000000u) : ~k;
    return __uint_as_float(b);
}
__device__ __forceinline__ float ex2(float x) {
    float y; asm("ex2.approx.ftz.f32 %0, %1;" : "=f"(y) : "f"(x)); return y;
}
__device__ __forceinline__ void mma16816h(unsigned* d, const unsigned* a, const unsigned* b) {
    asm volatile(
        "mma.sync.aligned.m16n8k16.row.col.f16.f16.f16.f16 "
        "{%0,%1}, {%2,%3,%4,%5}, {%6,%7}, {%0,%1};\n"
        : "+r"(d[0]), "+r"(d[1])
        : "r"(a[0]), "r"(a[1]), "r"(a[2]), "r"(a[3]), "r"(b[0]), "r"(b[1]));
}
__device__ __forceinline__ void ldsm4(unsigned& r0, unsigned& r1, unsigned& r2, unsigned& r3,
                                      unsigned addr) {
    asm volatile("ldmatrix.sync.aligned.m8n8.x4.shared.b16 {%0,%1,%2,%3}, [%4];\n"
                 : "=r"(r0), "=r"(r1), "=r"(r2), "=r"(r3) : "r"(addr));
}
__device__ __forceinline__ void cpasync16(unsigned daddr, const void* src) {
    asm volatile("cp.async.cg.shared.global [%0], [%1], 16;\n" :: "r"(daddr), "l"(src));
}
__device__ __forceinline__ void cpcommit() { asm volatile("cp.async.commit_group;\n"); }
template <int N> __device__ __forceinline__ void cpwait() {
    asm volatile("cp.async.wait_group %0;\n" :: "n"(N));
}

// ---------------- kernel 0 ----------------
__global__ void k_init(const float* __restrict__ temperature) {
    float t = temperature[0];
    float sp = (t > 20.f) ? t : log1pf(expf(t));
    g_C1 = LOG2E_F / sp;
    g_negMinK = 0xFFFFFFFFu; g_negMaxK = 0u;
    g_pvMinK  = 0xFFFFFFFFu; g_pvMaxK  = 0u;
    g_cnt = 0u;
}

// ---------------- kernel 1: normalize -> fp16 + pv minmax ----------------
__global__ void k_pre(const float* __restrict__ emb, const float* __restrict__ pv) {
    int row  = blockIdx.x * 8 + (threadIdx.x >> 5);
    int lane = threadIdx.x & 31;
    const float4* src = (const float4*)(emb + (size_t)row * ND);
    float4 v0 = src[lane * 2], v1 = src[lane * 2 + 1];
    float ss = v0.x*v0.x + v0.y*v0.y + v0.z*v0.z + v0.w*v0.w
             + v1.x*v1.x + v1.y*v1.y + v1.z*v1.z + v1.w*v1.w;
    #pragma unroll
    for (int off = 16; off; off >>= 1) ss += __shfl_xor_sync(0xffffffffu, ss, off);
    float inv = 1.f / fmaxf(sqrtf(ss), 1e-12f);
    __half2 o[4];
    o[0] = __floats2half2_rn(v0.x*inv, v0.y*inv);
    o[1] = __floats2half2_rn(v0.z*inv, v0.w*inv);
    o[2] = __floats2half2_rn(v1.x*inv, v1.y*inv);
    o[3] = __floats2half2_rn(v1.z*inv, v1.w*inv);
    *(uint4*)(g_z + (size_t)row * ND + lane * 8) = *(const uint4*)o;

    if (blockIdx.x < 64) {
        int i0 = (blockIdx.x * 256 + threadIdx.x) * 4;
        float4 v = *(const float4*)(pv + i0);
        float mn = fminf(fminf(v.x, v.y), fminf(v.z, v.w));
        float mx = fmaxf(fmaxf(v.x, v.y), fmaxf(v.z, v.w));
        #pragma unroll
        for (int off = 16; off; off >>= 1) {
            mn = fminf(mn, __shfl_xor_sync(0xffffffffu, mn, off));
            mx = fmaxf(mx, __shfl_xor_sync(0xffffffffu, mx, off));
        }
        __shared__ float smn[8], smx[8];
        int w = threadIdx.x >> 5;
        if (lane == 0) { smn[w] = mn; smx[w] = mx; }
        __syncthreads();
        if (threadIdx.x == 0) {
            float a = smn[0], b = smx[0];
            #pragma unroll
            for (int i = 1; i < 8; i++) { a = fminf(a, smn[i]); b = fmaxf(b, smx[i]); }
            atomicMin(&g_pvMinK, enc(a));
            atomicMax(&g_pvMaxK, enc(b));
        }
    }
}

// ---------------- kernel 2: triangular fp16 GEMM (f16 accum), 2-stage, occ 4 ----------------
__global__ __launch_bounds__(256, 4) void k_main() {
    extern __shared__ __align__(16) char smem[];
    __half* sABase = (__half*)smem;
    __half* sBBase = (__half*)(smem + OFF_SB);
    float* sRowA = (float*)(smem + OFF_ROWA);
    float* sRowB = (float*)(smem + OFF_ROWB);
    float* sColA = (float*)(smem + OFF_COLA);
    float* sColB = (float*)(smem + OFF_COLB);
    float* sMin  = (float*)(smem + OFF_MIN);
    float* sMax  = (float*)(smem + OFF_MAX);

    const int tid  = threadIdx.x;
    const int w    = tid >> 5, lane = tid & 31;
    const int wr   = w >> 1,   wc   = w & 1;              // warp grid 4x2, warp tile 32x64
    const int g    = lane >> 2, c   = lane & 3;

    // decode triangular tile index (row-major upper triangle)
    int rt = 0, rem = blockIdx.x;
    while (rem >= NT - rt) { rem -= NT - rt; rt++; }
    const int ct = rt + rem;
    const int rowA0 = rt * 128, rowB0 = ct * 128;

    // ldmatrix lane addressing (stage 0; add st*BUFM per stage)
    unsigned aAddr[2], bAddr[4];
    {
        int rowA = wr * 32 + (lane & 15);
        int colA = (lane >> 4) * 8;
        aAddr[0] = (unsigned)__cvta_generic_to_shared(&sABase[rowA * SROW + colA]);
        aAddr[1] = aAddr[0] + 16 * SROW * 2;
        int rowB = wc * 64 + (lane & 7) + ((lane & 16) ? 8 : 0);
        int colB = ((lane >> 3) & 1) * 8;
        unsigned b0 = (unsigned)__cvta_generic_to_shared(&sBBase[rowB * SROW + colB]);
        #pragma unroll
        for (int nj = 0; nj < 4; nj++) bAddr[nj] = b0 + nj * 16 * SROW * 2;
    }

    auto issue_chunk = [&](int st, int kc) {
        const int k0 = kc * CH;
        __half* dA = sABase + st * (BUFM / 2);
        __half* dB = sBBase + st * (BUFM / 2);
        #pragma unroll
        for (int itr = 0; itr < 2; itr++) {
            int idx = tid + itr * 256;
            int row = idx >> 2, q = idx & 3;
            cpasync16((unsigned)__cvta_generic_to_shared(&dA[row * SROW + q * 8]),
                      g_z + (size_t)(rowA0 + row) * ND + k0 + q * 8);
            cpasync16((unsigned)__cvta_generic_to_shared(&dB[row * SROW + q * 8]),
                      g_z + (size_t)(rowB0 + row) * ND + k0 + q * 8);
        }
        cpcommit();
    };

    unsigned acc[2][8][2];                                // f16x2 accumulators
    #pragma unroll
    for (int mi = 0; mi < 2; mi++)
        #pragma unroll
        for (int ni = 0; ni < 8; ni++)
            { acc[mi][ni][0] = 0u; acc[mi][ni][1] = 0u; }

    issue_chunk(0, 0);

    #pragma unroll
    for (int kc = 0; kc < ND / CH; kc++) {
        const int st = kc & 1;
        cpwait<0>();                                      // chunk kc ready
        __syncthreads();                                  // prev stage fully consumed
        if (kc + 1 < ND / CH) issue_chunk(st ^ 1, kc + 1);   // overlaps compute(kc)
        #pragma unroll
        for (int ks = 0; ks < 2; ks++) {
            const unsigned off = st * BUFM + ks * 32;     // ks*16 cols * 2B
            unsigned af[2][4], bfr[8][2];
            ldsm4(af[0][0], af[0][1], af[0][2], af[0][3], aAddr[0] + off);
            ldsm4(af[1][0], af[1][1], af[1][2], af[1][3], aAddr[1] + off);
            #pragma unroll
            for (int nj = 0; nj < 4; nj++) {
                unsigned r0, r1, r2, r3;
                ldsm4(r0, r1, r2, r3, bAddr[nj] + off);
                bfr[2*nj][0] = r0; bfr[2*nj][1] = r1;
                bfr[2*nj+1][0] = r2; bfr[2*nj+1][1] = r3;
            }
            #pragma unroll
            for (int mi = 0; mi < 2; mi++)
                #pragma unroll
                for (int ni = 0; ni < 8; ni++)
                    mma16816h(acc[mi][ni], af[mi], bfr[ni]);
        }
    }

    // ---- epilogue ----
    const float C1 = g_C1;
    const int dtile = ct - rt;
    const bool isDiag = (dtile == 0);
    const bool band = (dtile <= 1) || (dtile == 63);
    float rA4[4] = {0,0,0,0}, rB4[4] = {0,0,0,0};
    float cA[16], cB[16];
    float umin = __int_as_float(0x7f800000);
    float umax = __int_as_float(0xff800000);
    const int rowBase = rt * 128 + wr * 32;
    const int colBase = ct * 128 + wc * 64;
    #pragma unroll
    for (int ni = 0; ni < 8; ni++) {
        #pragma unroll
        for (int q = 0; q < 2; q++) {
            const int k = ni * 2 + q;
            float a = 0.f, bsum = 0.f;
            const int jG = colBase + ni * 8 + 2 * c + q;
            #pragma unroll
            for (int mi = 0; mi < 2; mi++)
            #pragma unroll
            for (int p = 0; p < 2; p++) {
                const int ai = mi * 2 + p;
                float2 fp2 = __half22float2(*(const __half2*)&acc[mi][ni][p]);
                float d = q ? fp2.y : fp2.x;
                float u = __fmaf_rn(d, C1, -C1);
                float e = ex2(u);
                float ue = u * e;
                rA4[ai] += e;  rB4[ai] += ue;
                a += e;        bsum += ue;
                if (!band) {
                    umin = fminf(umin, u); umax = fmaxf(umax, u);
                } else {
                    int iG = rowBase + mi * 16 + p * 8 + g;
                    int dd = (jG - iG) & (NB - 1);
                    if (isDiag) {
                        if (dd == 0)       g_uDiag[iG] = u;
                        else if (dd <= NK) g_uPos[iG * NK + dd - 1] = u;
                        else { umin = fminf(umin, u); umax = fmaxf(umax, u); }
                    } else {
                        if (dd <= NK)           g_uPos[iG * NK + dd - 1] = u;
                        else if (dd >= NB - NK) g_uPos[jG * NK + (NB - dd) - 1] = u;
                        umin = fminf(umin, u); umax = fmaxf(umax, u);
                    }
                }
            }
            cA[k] = a; cB[k] = bsum;
        }
    }
    if (!isDiag) {
        // split-butterfly over the 8 g-lanes (xor 4,8,16): 28 shuffles total
        #pragma unroll
        for (int step = 0; step < 3; step++) {
            const int mask = 4 << step;
            const int half = 8 >> step;
            const bool hi = (lane & mask) != 0;
            #pragma unroll
            for (int i = 0; i < half; i++) {
                float sa = hi ? cA[i] : cA[i + half];
                float ka = hi ? cA[i + half] : cA[i];
                cA[i] = ka + __shfl_xor_sync(0xffffffffu, sa, mask);
                float sb = hi ? cB[i] : cB[i + half];
                float kb = hi ? cB[i + half] : cB[i];
                cB[i] = kb + __shfl_xor_sync(0xffffffffu, sb, mask);
            }
        }
        const int ko2 = (g & 1) * 8 + ((g >> 1) & 1) * 4 + ((g >> 2) & 1) * 2;
        const int jl = wc * 64 + (ko2 >> 1) * 8 + 2 * c;
        *(float2*)&sColA[wr * 128 + jl] = make_float2(cA[0], cA[1]);
        *(float2*)&sColB[wr * 128 + jl] = make_float2(cB[0], cB[1]);
    }
    #pragma unroll
    for (int ai = 0; ai < 4; ai++) {
        float a = rA4[ai], bb = rB4[ai];
        a  += __shfl_xor_sync(0xffffffffu, a, 1);  a  += __shfl_xor_sync(0xffffffffu, a, 2);
        bb += __shfl_xor_sync(0xffffffffu, bb, 1); bb += __shfl_xor_sync(0xffffffffu, bb, 2);
        if (c == 0) {
            int rloc = wr * 32 + (ai >> 1) * 16 + (ai & 1) * 8 + g;
            sRowA[wc * 128 + rloc] = a; sRowB[wc * 128 + rloc] = bb;
        }
    }
    #pragma unroll
    for (int off = 16; off; off >>= 1) {
        umin = fminf(umin, __shfl_xor_sync(0xffffffffu, umin, off));
        umax = fmaxf(umax, __shfl_xor_sync(0xffffffffu, umax, off));
    }
    if (lane == 0) { sMin[w] = umin; sMax[w] = umax; }
    __syncthreads();
    if (tid < 128) {
        g_Apart[ct * NB + rt * 128 + tid] = sRowA[tid] + sRowA[128 + tid];
        g_Bpart[ct * NB + rt * 128 + tid] = sRowB[tid] + sRowB[128 + tid];
    } else if (!isDiag) {
        int t2 = tid - 128;
        g_Apart[rt * NB + ct * 128 + t2] =
            (sColA[t2] + sColA[128 + t2]) + (sColA[256 + t2] + sColA[384 + t2]);
        g_Bpart[rt * NB + ct * 128 + t2] =
            (sColB[t2] + sColB[128 + t2]) + (sColB[256 + t2] + sColB[384 + t2]);
    }
    if (tid == 0) {
        float mn = sMin[0], mx = sMax[0];
        #pragma unroll
        for (int i = 1; i < 8; i++) { mn = fminf(mn, sMin[i]); mx = fmaxf(mx, sMax[i]); }
        atomicMin(&g_negMinK, enc(mn));
        atomicMax(&g_negMaxK, enc(mx));
    }
}

// ---------------- kernel 3: log-denominator + weighted pos + final ----------------
// 512 blocks x 256 thr. Block owns 16 rows; 8 warps each cover 8 of the 64
// slab slots (lane&15 = row -> 64B-coalesced; lane>>4 selects slot pair).
__global__ void k_fin1(const float* __restrict__ pv, float* __restrict__ out) {
    __shared__ float sA_[8][16], sB_[8][16];
    __shared__ bool last;
    const int w = threadIdx.x >> 5, lane = threadIdx.x & 31;
    const int r = lane & 15, h = lane >> 4;
    const int row0 = blockIdx.x * 16;

    float A = 0.f, Bp = 0.f;
    #pragma unroll
    for (int j = 0; j < 4; j++) {                         // slots w*8 + j*2 + h
        const int t = w * 8 + j * 2 + h;
        A  += g_Apart[t * NB + row0 + r];
        Bp += g_Bpart[t * NB + row0 + r];
    }
    A  += __shfl_xor_sync(0xffffffffu, A, 16);
    Bp += __shfl_xor_sync(0xffffffffu, Bp, 16);
    if (h == 0) { sA_[w][r] = A; sB_[w][r] = Bp; }
    __syncthreads();

    float accv = 0.f;
    if (threadIdx.x < 16) {                               // one thread per row
        const int row = row0 + threadIdx.x;
        float As = 0.f, Bs = 0.f;
        #pragma unroll
        for (int i = 0; i < 8; i++) { As += sA_[i][threadIdx.x]; Bs += sB_[i][threadIdx.x]; }

        float4 up0 = *(const float4*)(g_uPos + row * NK);
        float4 up1 = *(const float4*)(g_uPos + row * NK + 4);
        float u[NK] = {up0.x, up0.y, up0.z, up0.w, up1.x, up1.y, up1.z, up1.w};
        float uD = g_uDiag[row];
        float eD = ex2(uD);
        float sumE = eD, sumSE = uD * eD;
        #pragma unroll
        for (int k = 0; k < NK; k++) {
            float e = ex2(u[k]);
            sumE  += e;
            sumSE += u[k] * e;
        }
        sumSE *= LN2_F;

        float Bn   = Bs * LN2_F;
        float nmin = dec(g_negMinK) * LN2_F;
        float nmax = dec(g_negMaxK) * LN2_F;
        float Aneg = As - sumE;
        float Bneg = Bn - sumSE;
        float ld = logf(As + (Bneg - nmin * Aneg) / (nmax - nmin + 1e-8f));

        float pvMax = dec(g_pvMaxK), pvMin = dec(g_pvMinK);
        float invPr = 1.f / ((pvMax - pvMin) + 1e-8f);
        float4 pvv0 = *(const float4*)(pv + row * NK);
        float4 pvv1 = *(const float4*)(pv + row * NK + 4);
        float pw[NK] = {pvv0.x, pvv0.y, pvv0.z, pvv0.w, pvv1.x, pvv1.y, pvv1.z, pvv1.w};
        #pragma unroll
        for (int k = 0; k < NK; k++)
            accv += (u[k] * LN2_F - ld) * ((pvMax - pw[k]) * invPr);

        #pragma unroll
        for (int off = 8; off; off >>= 1) accv += __shfl_xor_sync(0x0000ffffu, accv, off);
        if (threadIdx.x == 0) {
            g_red[blockIdx.x] = accv;
            __threadfence();
            unsigned t = atomicAdd(&g_cnt, 1u);
            last = (t == 511u);
        }
    }
    __syncthreads();
    if (last) {
        __threadfence();
        float v = g_red[threadIdx.x] + g_red[threadIdx.x + 256];
        #pragma unroll
        for (int off = 16; off; off >>= 1) v += __shfl_xor_sync(0xffffffffu, v, off);
        __shared__ float sp2[8];
        if ((threadIdx.x & 31) == 0) sp2[threadIdx.x >> 5] = v;
        __syncthreads();
        if (threadIdx.x == 0) {
            float s = 0.f;
            #pragma unroll
            for (int i = 0; i < 8; i++) s += sp2[i];
            out[0] = -s * (1.f / (NB * NK));
        }
    }
}

// ---------------- launch ----------------
extern "C" void kernel_launch(void* const* d_in, const int* in_sizes, int n_in,
                              void* d_out, int out_size) {
    const float* emb  = (const float*)d_in[0];
    const float* pv   = (const float*)d_in[1];
    const float* temp = (const float*)d_in[2];
    float* out = (float*)d_out;
    (void)in_sizes; (void)n_in; (void)out_size;

    cudaFuncSetAttribute(k_main, cudaFuncAttributeMaxDynamicSharedMemorySize, SMEM_TOTAL);

    k_init<<<1, 1>>>(temp);
    k_pre<<<NB / 8, 256>>>(emb, pv);
    k_main<<<NTILE, 256, SMEM_TOTAL>>>();
    k_fin1<<<512, 256>>>(pv, out);
}

// round 15
// speedup vs baseline: 1.0588x; 1.0588x over previous
#include <cuda_runtime.h>
#include <cuda_fp16.h>
#include <cstdint>

#define NB 8192
#define ND 256
#define NK 8
#define NT 64
#define NTILE 2080        // 64*65/2 upper-triangular tiles
#define LOG2E_F 1.4426950408889634f
#define LN2_F   0.6931471805599453f
#define CH 32             // K elements per pipeline stage
#define SROW 40           // padded fp16 row (80B): conflict-free ldmatrix
#define BUFM (128 * SROW * 2)    // 10240 B per matrix per stage

// dynamic smem layout (bytes): 3 stages -> 3 CTAs/SM
#define OFF_SB   (3 * BUFM)
#define OFF_ROWA (6 * BUFM)
#define OFF_ROWB (OFF_ROWA + 1024)
#define OFF_COLA (OFF_ROWB + 1024)
#define OFF_COLB (OFF_COLA + 2048)
#define OFF_MIN  (OFF_COLB + 2048)
#define OFF_MAX  (OFF_MIN + 32)
#define SMEM_TOTAL (OFF_MAX + 32)       // 67712 B

// ---------------- device scratch (statics init run 1; k_fin1 resets for replays) ----------------
__device__ __align__(16) __half g_z[NB * ND];
__device__ float g_Apart[NT * NB];               // [slot*NB + row]
__device__ float g_Bpart[NT * NB];
__device__ __align__(16) float g_uPos[NB * NK];
__device__ float g_uDiag[NB];
__device__ float g_red[512];
__device__ unsigned g_negMinK = 0xFFFFFFFFu;
__device__ unsigned g_negMaxK = 0u;
__device__ unsigned g_pvMinK  = 0xFFFFFFFFu;
__device__ unsigned g_pvMaxK  = 0u;
__device__ unsigned g_cnt = 0u;
__device__ float g_C1;

// ---------------- helpers ----------------
__device__ __forceinline__ unsigned enc(float f) {
    unsigned b = __float_as_uint(f);
    return (b & 0x80000000u) ? ~b : (b | 0x80000000u);
}
__device__ __forceinline__ float dec(unsigned k) {
    unsigned b = (k & 0x80000000u) ? (k ^ 0x80000000u) : ~k;
    return __uint_as_float(b);
}
__device__ __forceinline__ float ex2(float x) {
    float y; asm("ex2.approx.ftz.f32 %0, %1;" : "=f"(y) : "f"(x)); return y;
}
__device__ __forceinline__ void mma16816h(unsigned* d, const unsigned* a, const unsigned* b) {
    asm volatile(
        "mma.sync.aligned.m16n8k16.row.col.f16.f16.f16.f16 "
        "{%0,%1}, {%2,%3,%4,%5}, {%6,%7}, {%0,%1};\n"
        : "+r"(d[0]), "+r"(d[1])
        : "r"(a[0]), "r"(a[1]), "r"(a[2]), "r"(a[3]), "r"(b[0]), "r"(b[1]));
}
__device__ __forceinline__ void ldsm4(unsigned& r0, unsigned& r1, unsigned& r2, unsigned& r3,
                                      unsigned addr) {
    asm volatile("ldmatrix.sync.aligned.m8n8.x4.shared.b16 {%0,%1,%2,%3}, [%4];\n"
                 : "=r"(r0), "=r"(r1), "=r"(r2), "=r"(r3) : "r"(addr));
}
__device__ __forceinline__ void cpasync16(unsigned daddr, const void* src) {
    asm volatile("cp.async.cg.shared.global [%0], [%1], 16;\n" :: "r"(daddr), "l"(src));
}
__device__ __forceinline__ void cpcommit() { asm volatile("cp.async.commit_group;\n"); }
template <int N> __device__ __forceinline__ void cpwait() {
    asm volatile("cp.async.wait_group %0;\n" :: "n"(N));
}

// ---------------- kernel 1: normalize -> fp16 + pv minmax + scalar setup ----------------
__global__ void k_pre(const float* __restrict__ emb, const float* __restrict__ pv,
                      const float* __restrict__ temperature) {
    if (blockIdx.x == 0 && threadIdx.x == 0) {
        float t = temperature[0];
        float sp = (t > 20.f) ? t : log1pf(expf(t));
        g_C1 = LOG2E_F / sp;                              // visible to k_main (kernel boundary)
    }
    int row  = blockIdx.x * 8 + (threadIdx.x >> 5);
    int lane = threadIdx.x & 31;
    const float4* src = (const float4*)(emb + (size_t)row * ND);
    float4 v0 = src[lane * 2], v1 = src[lane * 2 + 1];
    float ss = v0.x*v0.x + v0.y*v0.y + v0.z*v0.z + v0.w*v0.w
             + v1.x*v1.x + v1.y*v1.y + v1.z*v1.z + v1.w*v1.w;
    #pragma unroll
    for (int off = 16; off; off >>= 1) ss += __shfl_xor_sync(0xffffffffu, ss, off);
    float inv = 1.f / fmaxf(sqrtf(ss), 1e-12f);
    __half2 o[4];
    o[0] = __floats2half2_rn(v0.x*inv, v0.y*inv);
    o[1] = __floats2half2_rn(v0.z*inv, v0.w*inv);
    o[2] = __floats2half2_rn(v1.x*inv, v1.y*inv);
    o[3] = __floats2half2_rn(v1.z*inv, v1.w*inv);
    *(uint4*)(g_z + (size_t)row * ND + lane * 8) = *(const uint4*)o;

    if (blockIdx.x < 64) {
        int i0 = (blockIdx.x * 256 + threadIdx.x) * 4;
        float4 v = *(const float4*)(pv + i0);
        float mn = fminf(fminf(v.x, v.y), fminf(v.z, v.w));
        float mx = fmaxf(fmaxf(v.x, v.y), fmaxf(v.z, v.w));
        #pragma unroll
        for (int off = 16; off; off >>= 1) {
            mn = fminf(mn, __shfl_xor_sync(0xffffffffu, mn, off));
            mx = fmaxf(mx, __shfl_xor_sync(0xffffffffu, mx, off));
        }
        __shared__ float smn[8], smx[8];
        int w = threadIdx.x >> 5;
        if (lane == 0) { smn[w] = mn; smx[w] = mx; }
        __syncthreads();
        if (threadIdx.x == 0) {
            float a = smn[0], b = smx[0];
            #pragma unroll
            for (int i = 1; i < 8; i++) { a = fminf(a, smn[i]); b = fmaxf(b, smx[i]); }
            atomicMin(&g_pvMinK, enc(a));
            atomicMax(&g_pvMaxK, enc(b));
        }
    }
}

// ---------------- kernel 2: triangular fp16 GEMM (f16 accum) + exp-sum epilogue ----------------
__global__ __launch_bounds__(256, 3) void k_main() {
    extern __shared__ __align__(16) char smem[];
    __half* sABase = (__half*)smem;
    __half* sBBase = (__half*)(smem + OFF_SB);
    float* sRowA = (float*)(smem + OFF_ROWA);
    float* sRowB = (float*)(smem + OFF_ROWB);
    float* sColA = (float*)(smem + OFF_COLA);
    float* sColB = (float*)(smem + OFF_COLB);
    float* sMin  = (float*)(smem + OFF_MIN);
    float* sMax  = (float*)(smem + OFF_MAX);

    const int tid  = threadIdx.x;
    const int w    = tid >> 5, lane = tid & 31;
    const int wr   = w >> 1,   wc   = w & 1;              // warp grid 4x2, warp tile 32x64
    const int g    = lane >> 2, c   = lane & 3;

    // decode triangular tile index (row-major upper triangle)
    int rt = 0, rem = blockIdx.x;
    while (rem >= NT - rt) { rem -= NT - rt; rt++; }
    const int ct = rt + rem;
    const int rowA0 = rt * 128, rowB0 = ct * 128;

    // ldmatrix lane addressing (stage 0; add st*BUFM per stage)
    unsigned aAddr[2], bAddr[4];
    {
        int rowA = wr * 32 + (lane & 15);
        int colA = (lane >> 4) * 8;
        aAddr[0] = (unsigned)__cvta_generic_to_shared(&sABase[rowA * SROW + colA]);
        aAddr[1] = aAddr[0] + 16 * SROW * 2;
        int rowB = wc * 64 + (lane & 7) + ((lane & 16) ? 8 : 0);
        int colB = ((lane >> 3) & 1) * 8;
        unsigned b0 = (unsigned)__cvta_generic_to_shared(&sBBase[rowB * SROW + colB]);
        #pragma unroll
        for (int nj = 0; nj < 4; nj++) bAddr[nj] = b0 + nj * 16 * SROW * 2;
    }

    auto issue_chunk = [&](int st, int kc) {
        const int k0 = kc * CH;
        __half* dA = sABase + st * (BUFM / 2);
        __half* dB = sBBase + st * (BUFM / 2);
        #pragma unroll
        for (int itr = 0; itr < 2; itr++) {
            int idx = tid + itr * 256;
            int row = idx >> 2, q = idx & 3;
            cpasync16((unsigned)__cvta_generic_to_shared(&dA[row * SROW + q * 8]),
                      g_z + (size_t)(rowA0 + row) * ND + k0 + q * 8);
            cpasync16((unsigned)__cvta_generic_to_shared(&dB[row * SROW + q * 8]),
                      g_z + (size_t)(rowB0 + row) * ND + k0 + q * 8);
        }
        cpcommit();
    };

    unsigned acc[2][8][2];                                // f16x2 accumulators
    #pragma unroll
    for (int mi = 0; mi < 2; mi++)
        #pragma unroll
        for (int ni = 0; ni < 8; ni++)
            { acc[mi][ni][0] = 0u; acc[mi][ni][1] = 0u; }

    issue_chunk(0, 0);
    issue_chunk(1, 1);

    #pragma unroll
    for (int kc = 0; kc < ND / CH; kc++) {
        const int st = kc % 3;
        if (kc == ND / CH - 1) cpwait<0>(); else cpwait<1>();
        __syncthreads();                                   // single barrier per chunk
        if (kc + 2 < ND / CH) issue_chunk((kc + 2) % 3, kc + 2);
        #pragma unroll
        for (int ks = 0; ks < 2; ks++) {
            const unsigned off = st * BUFM + ks * 32;      // ks*16 cols * 2B
            unsigned af[2][4], bfr[8][2];
            ldsm4(af[0][0], af[0][1], af[0][2], af[0][3], aAddr[0] + off);
            ldsm4(af[1][0], af[1][1], af[1][2], af[1][3], aAddr[1] + off);
            #pragma unroll
            for (int nj = 0; nj < 4; nj++) {
                unsigned r0, r1, r2, r3;
                ldsm4(r0, r1, r2, r3, bAddr[nj] + off);
                bfr[2*nj][0] = r0; bfr[2*nj][1] = r1;
                bfr[2*nj+1][0] = r2; bfr[2*nj+1][1] = r3;
            }
            #pragma unroll
            for (int mi = 0; mi < 2; mi++)
                #pragma unroll
                for (int ni = 0; ni < 8; ni++)
                    mma16816h(acc[mi][ni], af[mi], bfr[ni]);
        }
    }

    // ---- epilogue ----
    const float C1 = g_C1;
    const int dtile = ct - rt;
    const bool isDiag = (dtile == 0);
    const bool band = (dtile <= 1) || (dtile == 63);
    float rA4[4] = {0,0,0,0}, rB4[4] = {0,0,0,0};
    float cA[16], cB[16];
    float umin = __int_as_float(0x7f800000);
    float umax = __int_as_float(0xff800000);
    const int rowBase = rt * 128 + wr * 32;
    const int colBase = ct * 128 + wc * 64;
    #pragma unroll
    for (int ni = 0; ni < 8; ni++) {
        #pragma unroll
        for (int q = 0; q < 2; q++) {
            const int k = ni * 2 + q;
            float a = 0.f, bsum = 0.f;
            const int jG = colBase + ni * 8 + 2 * c + q;
            #pragma unroll
            for (int mi = 0; mi < 2; mi++)
            #pragma unroll
            for (int p = 0; p < 2; p++) {
                const int ai = mi * 2 + p;
                float2 fp2 = __half22float2(*(const __half2*)&acc[mi][ni][p]);
                float d = q ? fp2.y : fp2.x;
                float u = __fmaf_rn(d, C1, -C1);
                float e = ex2(u);
                float ue = u * e;
                rA4[ai] += e;  rB4[ai] += ue;
                a += e;        bsum += ue;
                if (!band) {
                    umin = fminf(umin, u); umax = fmaxf(umax, u);
                } else {
                    int iG = rowBase + mi * 16 + p * 8 + g;
                    int dd = (jG - iG) & (NB - 1);
                    if (isDiag) {
                        if (dd == 0)       g_uDiag[iG] = u;
                        else if (dd <= NK) g_uPos[iG * NK + dd - 1] = u;
                        else { umin = fminf(umin, u); umax = fmaxf(umax, u); }
                    } else {
                        if (dd <= NK)           g_uPos[iG * NK + dd - 1] = u;
                        else if (dd >= NB - NK) g_uPos[jG * NK + (NB - dd) - 1] = u;
                        umin = fminf(umin, u); umax = fmaxf(umax, u);
                    }
                }
            }
            cA[k] = a; cB[k] = bsum;
        }
    }
    if (!isDiag) {
        // split-butterfly over the 8 g-lanes (xor 4,8,16): 28 shuffles total
        #pragma unroll
        for (int step = 0; step < 3; step++) {
            const int mask = 4 << step;
            const int half = 8 >> step;
            const bool hi = (lane & mask) != 0;
            #pragma unroll
            for (int i = 0; i < half; i++) {
                float sa = hi ? cA[i] : cA[i + half];
                float ka = hi ? cA[i + half] : cA[i];
                cA[i] = ka + __shfl_xor_sync(0xffffffffu, sa, mask);
                float sb = hi ? cB[i] : cB[i + half];
                float kb = hi ? cB[i + half] : cB[i];
                cB[i] = kb + __shfl_xor_sync(0xffffffffu, sb, mask);
            }
        }
        const int ko2 = (g & 1) * 8 + ((g >> 1) & 1) * 4 + ((g >> 2) & 1) * 2;
        const int jl = wc * 64 + (ko2 >> 1) * 8 + 2 * c;
        *(float2*)&sColA[wr * 128 + jl] = make_float2(cA[0], cA[1]);
        *(float2*)&sColB[wr * 128 + jl] = make_float2(cB[0], cB[1]);
    }
    #pragma unroll
    for (int ai = 0; ai < 4; ai++) {
        float a = rA4[ai], bb = rB4[ai];
        a  += __shfl_xor_sync(0xffffffffu, a, 1);  a  += __shfl_xor_sync(0xffffffffu, a, 2);
        bb += __shfl_xor_sync(0xffffffffu, bb, 1); bb += __shfl_xor_sync(0xffffffffu, bb, 2);
        if (c == 0) {
            int rloc = wr * 32 + (ai >> 1) * 16 + (ai & 1) * 8 + g;
            sRowA[wc * 128 + rloc] = a; sRowB[wc * 128 + rloc] = bb;
        }
    }
    #pragma unroll
    for (int off = 16; off; off >>= 1) {
        umin = fminf(umin, __shfl_xor_sync(0xffffffffu, umin, off));
        umax = fmaxf(umax, __shfl_xor_sync(0xffffffffu, umax, off));
    }
    if (lane == 0) { sMin[w] = umin; sMax[w] = umax; }
    __syncthreads();
    if (tid < 128) {
        g_Apart[ct * NB + rt * 128 + tid] = sRowA[tid] + sRowA[128 + tid];
        g_Bpart[ct * NB + rt * 128 + tid] = sRowB[tid] + sRowB[128 + tid];
    } else if (!isDiag) {
        int t2 = tid - 128;
        g_Apart[rt * NB + ct * 128 + t2] =
            (sColA[t2] + sColA[128 + t2]) + (sColA[256 + t2] + sColA[384 + t2]);
        g_Bpart[rt * NB + ct * 128 + t2] =
            (sColB[t2] + sColB[128 + t2]) + (sColB[256 + t2] + sColB[384 + t2]);
    }
    if (tid == 0) {
        float mn = sMin[0], mx = sMax[0];
        #pragma unroll
        for (int i = 1; i < 8; i++) { mn = fminf(mn, sMin[i]); mx = fmaxf(mx, sMax[i]); }
        atomicMin(&g_negMinK, enc(mn));
        atomicMax(&g_negMaxK, enc(mx));
    }
}

// ---------------- kernel 3: log-denominator + weighted pos + final + state reset ----------------
// 512 blocks x 256 thr. Block owns 16 rows; 8 warps each cover 8 of the 64
// slab slots (lane&15 = row -> 64B-coalesced; lane>>4 selects slot pair).
__global__ void k_fin1(const float* __restrict__ pv, float* __restrict__ out) {
    __shared__ float sA_[8][16], sB_[8][16];
    __shared__ bool last;
    const int w = threadIdx.x >> 5, lane = threadIdx.x & 31;
    const int r = lane & 15, h = lane >> 4;
    const int row0 = blockIdx.x * 16;

    float A = 0.f, Bp = 0.f;
    #pragma unroll
    for (int j = 0; j < 4; j++) {                         // slots w*8 + j*2 + h
        const int t = w * 8 + j * 2 + h;
        A  += g_Apart[t * NB + row0 + r];
        Bp += g_Bpart[t * NB + row0 + r];
    }
    A  += __shfl_xor_sync(0xffffffffu, A, 16);
    Bp += __shfl_xor_sync(0xffffffffu, Bp, 16);
    if (h == 0) { sA_[w][r] = A; sB_[w][r] = Bp; }
    __syncthreads();

    float accv = 0.f;
    if (threadIdx.x < 16) {                               // one thread per row
        const int row = row0 + threadIdx.x;
        float As = 0.f, Bs = 0.f;
        #pragma unroll
        for (int i = 0; i < 8; i++) { As += sA_[i][threadIdx.x]; Bs += sB_[i][threadIdx.x]; }

        float4 up0 = *(const float4*)(g_uPos + row * NK);
        float4 up1 = *(const float4*)(g_uPos + row * NK + 4);
        float u[NK] = {up0.x, up0.y, up0.z, up0.w, up1.x, up1.y, up1.z, up1.w};
        float uD = g_uDiag[row];
        float eD = ex2(uD);
        float sumE = eD, sumSE = uD * eD;
        #pragma unroll
        for (int k = 0; k < NK; k++) {
            float e = ex2(u[k]);
            sumE  += e;
            sumSE += u[k] * e;
        }
        sumSE *= LN2_F;

        float Bn   = Bs * LN2_F;
        float nmin = dec(g_negMinK) * LN2_F;
        float nmax = dec(g_negMaxK) * LN2_F;
        float Aneg = As - sumE;
        float Bneg = Bn - sumSE;
        float ld = logf(As + (Bneg - nmin * Aneg) / (nmax - nmin + 1e-8f));

        float pvMax = dec(g_pvMaxK), pvMin = dec(g_pvMinK);
        float invPr = 1.f / ((pvMax - pvMin) + 1e-8f);
        float4 pvv0 = *(const float4*)(pv + row * NK);
        float4 pvv1 = *(const float4*)(pv + row * NK + 4);
        float pw[NK] = {pvv0.x, pvv0.y, pvv0.z, pvv0.w, pvv1.x, pvv1.y, pvv1.z, pvv1.w};
        #pragma unroll
        for (int k = 0; k < NK; k++)
            accv += (u[k] * LN2_F - ld) * ((pvMax - pw[k]) * invPr);

        #pragma unroll
        for (int off = 8; off; off >>= 1) accv += __shfl_xor_sync(0x0000ffffu, accv, off);
        if (threadIdx.x == 0) {
            g_red[blockIdx.x] = accv;
            __threadfence();
            unsigned t = atomicAdd(&g_cnt, 1u);
            last = (t == 511u);
        }
    }
    __syncthreads();
    if (last) {
        __threadfence();
        float v = g_red[threadIdx.x] + g_red[threadIdx.x + 256];
        #pragma unroll
        for (int off = 16; off; off >>= 1) v += __shfl_xor_sync(0xffffffffu, v, off);
        __shared__ float sp2[8];
        if ((threadIdx.x & 31) == 0) sp2[threadIdx.x >> 5] = v;
        __syncthreads();
        if (threadIdx.x == 0) {
            float s = 0.f;
            #pragma unroll
            for (int i = 0; i < 8; i++) s += sp2[i];
            out[0] = -s * (1.f / (NB * NK));
            // reset global state for the next graph replay (stream-ordered
            // before the next invocation's k_pre/k_main atomics)
            g_negMinK = 0xFFFFFFFFu; g_negMaxK = 0u;
            g_pvMinK  = 0xFFFFFFFFu; g_pvMaxK  = 0u;
            g_cnt = 0u;
        }
    }
}

// ---------------- launch ----------------
extern "C" void kernel_launch(void* const* d_in, const int* in_sizes, int n_in,
                              void* d_out, int out_size) {
    const float* emb  = (const float*)d_in[0];
    const float* pv   = (const float*)d_in[1];
    const float* temp = (const float*)d_in[2];
    float* out = (float*)d_out;
    (void)in_sizes; (void)n_in; (void)out_size;

    cudaFuncSetAttribute(k_main, cudaFuncAttributeMaxDynamicSharedMemorySize, SMEM_TOTAL);

    k_pre<<<NB / 8, 256>>>(emb, pv, temp);
    k_main<<<NTILE, 256, SMEM_TOTAL>>>();
    k_fin1<<<512, 256>>>(pv, out);
}